// round 15
// baseline (speedup 1.0000x reference)
#include <cuda_runtime.h>
#include <cuda_bf16.h>
#include <cuda_fp16.h>
#include <math.h>
#include <stdint.h>

#define BB 2
#define LL 4096
#define DD 1024
#define HH 16
#define DH 64
#define FF 4096
#define ROWS (BB*LL)   // 8192
#define QKVN 3072
#define LOG2E 1.4426950408889634f

// ---------------- scratch ----------------
__device__ __half g_xh[ROWS * DD];
__device__ __half g_qkvh[ROWS * QKVN];   // packed q|k|v per row
__device__ __half g_attnh[ROWS * DD];    // attention out (f16)
__device__ __half g_hnh[ROWS * DD];      // LN out f16 (GEMM operand + residual)
__device__ __half g_acth[ROWS * FF];
__device__ __half g_wqkvt[QKVN * DD];    // [Wq^T ; Wk^T ; Wv^T]
__device__ float  g_bqkv[QKVN];
__device__ __half g_w1t[DD * FF];
__device__ __half g_w2t[FF * DD];

// =====================  helpers  =====================
__device__ __forceinline__ uint32_t smem_to_u32(const void* p) {
    uint32_t a;
    asm("{ .reg .u64 t; cvta.to.shared.u64 t, %1; cvt.u32.u64 %0, t; }" : "=r"(a) : "l"(p));
    return a;
}

#define CP_ASYNC16(dst, src) \
    asm volatile("cp.async.cg.shared.global [%0], [%1], 16;" :: "r"(dst), "l"(src))
#define CP_COMMIT() asm volatile("cp.async.commit_group;" ::: "memory")
#define CP_WAITG1() asm volatile("cp.async.wait_group 1;" ::: "memory")

#define LDSM_X4(r0, r1, r2, r3, addr) \
    asm volatile("ldmatrix.sync.aligned.m8n8.x4.shared.b16 {%0,%1,%2,%3}, [%4];" \
        : "=r"(r0), "=r"(r1), "=r"(r2), "=r"(r3) : "r"(addr))
#define LDSM_X4_T(r0, r1, r2, r3, addr) \
    asm volatile("ldmatrix.sync.aligned.m8n8.x4.trans.shared.b16 {%0,%1,%2,%3}, [%4];" \
        : "=r"(r0), "=r"(r1), "=r"(r2), "=r"(r3) : "r"(addr))

__device__ __forceinline__ void mma_f16(float* d, uint32_t a0, uint32_t a1,
                                        uint32_t a2, uint32_t a3,
                                        uint32_t b0, uint32_t b1) {
    asm volatile(
        "mma.sync.aligned.m16n8k16.row.col.f32.f16.f16.f32 "
        "{%0,%1,%2,%3}, {%4,%5,%6,%7}, {%8,%9}, {%0,%1,%2,%3};"
        : "+f"(d[0]), "+f"(d[1]), "+f"(d[2]), "+f"(d[3])
        : "r"(a0), "r"(a1), "r"(a2), "r"(a3), "r"(b0), "r"(b1));
}

__device__ __forceinline__ uint32_t ex2h2(uint32_t x) {
    uint32_t r; asm("ex2.approx.f16x2 %0, %1;" : "=r"(r) : "r"(x)); return r;
}
__device__ __forceinline__ uint32_t packh2(float lo, float hi) {
    uint32_t r; asm("cvt.rn.f16x2.f32 %0, %1, %2;" : "=r"(r) : "f"(hi), "f"(lo)); return r;
}
__device__ __forceinline__ uint32_t hmul2u(uint32_t a, uint32_t b) {
    uint32_t r; asm("mul.f16x2 %0, %1, %2;" : "=r"(r) : "r"(a), "r"(b)); return r;
}

// =====================  fused preprocessing kernel (R13)  =====================
__device__ __forceinline__ void transpose_tile(const float* __restrict__ in,
                                               __half* __restrict__ out,
                                               int R, int C, int bx, int by,
                                               float* t, int tid)
{
    const int tx = tid & 31;
    const int ty = tid >> 5;
    const int x = bx * 32 + tx;
#pragma unroll
    for (int i = 0; i < 32; i += 8) {
        const int y = by * 32 + ty + i;
        t[(ty + i) * 33 + tx] = in[(size_t)y * C + x];
    }
    __syncthreads();
    const int x2 = by * 32 + tx;
#pragma unroll
    for (int i = 0; i < 32; i += 8) {
        const int y2 = bx * 32 + ty + i;
        out[(size_t)y2 * R + x2] = __float2half_rn(t[tx * 33 + ty + i]);
    }
}

__global__ __launch_bounds__(256)
void prep_kernel(const float* __restrict__ x,
                 const float* __restrict__ Wq, const float* __restrict__ Wk,
                 const float* __restrict__ Wv, const float* __restrict__ W1,
                 const float* __restrict__ W2,
                 const float* __restrict__ bq, const float* __restrict__ bk,
                 const float* __restrict__ bv)
{
    __shared__ float t[32 * 33];
    const int blk = blockIdx.x;
    const int tid = threadIdx.x;

    if (blk < 8192) {
        const int i = blk * 256 + tid;
        const float4 f = *reinterpret_cast<const float4*>(x + (size_t)i * 4);
        uint2 u;
        u.x = packh2(f.x, f.y);
        u.y = packh2(f.z, f.w);
        *reinterpret_cast<uint2*>(g_xh + (size_t)i * 4) = u;
    } else if (blk < 11264) {
        const int r = blk - 8192;
        const int z = r >> 10;
        const int tI = r & 1023;
        const float* in = (z == 0) ? Wq : (z == 1) ? Wk : Wv;
        transpose_tile(in, g_wqkvt + (size_t)z * DD * DD, DD, DD,
                       tI & 31, tI >> 5, t, tid);
    } else if (blk < 15360) {
        const int r = blk - 11264;
        transpose_tile(W1, g_w1t, DD, FF, r & 127, r >> 7, t, tid);
    } else if (blk < 19456) {
        const int r = blk - 15360;
        transpose_tile(W2, g_w2t, FF, DD, r & 31, r >> 5, t, tid);
    } else {
        const int i = (blk - 19456) * 256 + tid;
        if (i < 1024) g_bqkv[i] = bq[i];
        else if (i < 2048) g_bqkv[i] = bk[i - 1024];
        else if (i < 3072) g_bqkv[i] = bv[i - 2048];
    }
}

// =====================  f16 mma.sync GEMM, 256x128x64 tile, 3-stage, 1 barrier/chunk  =====================
static constexpr int GROWB = 144;                         // 64 halves + 8 pad
static constexpr int GA_BYTES = 256 * GROWB;              // 36864
static constexpr int GSTG_BYTES = GA_BYTES + 128 * GROWB; // 55296
static constexpr uint32_t GEMM_DSMEM = 3 * GSTG_BYTES;    // 165888

// EPI 0: *= alpha -> half ; EPI 1: gelu -> half ; EPI 2: += Rh (f16 residual) -> fp32
template<int EPI>
__global__ __launch_bounds__(256, 1)
void hgemm(const __half* __restrict__ A, const __half* __restrict__ Bt,
           const float* __restrict__ bias, const __half* __restrict__ Rh,
           void* __restrict__ Cout, int M, int N, int K, float alpha)
{
    extern __shared__ char dsm[];
    const uint32_t smem_u = smem_to_u32(dsm);
    const int tid = threadIdx.x;
    const int wid = tid >> 5;
    const int lane = tid & 31;
    const int gid = lane >> 2;
    const int tg = lane & 3;
    const int warp_m = wid & 3;
    const int warp_n = wid >> 2;
    const int row0 = blockIdx.y * 256;
    const int col0 = blockIdx.x * 128;
    const int nk = K >> 6;   // K chunks of 64

    float acc[4][8][4];
#pragma unroll
    for (int i = 0; i < 4; i++)
#pragma unroll
        for (int j = 0; j < 8; j++)
#pragma unroll
            for (int q = 0; q < 4; q++) acc[i][j][q] = 0.f;

    const uint32_t aOff = (uint32_t)(warp_m * 64 + (lane & 15)) * GROWB + (lane >> 4) * 16;
    const uint32_t bOff = (uint32_t)GA_BYTES
                        + (uint32_t)(warp_n * 64 + ((lane >> 4) & 1) * 8 + (lane & 7)) * GROWB
                        + ((lane >> 3) & 1) * 16;

    auto load_stage = [&](int s, int kc) {
        const uint32_t sA = smem_u + s * GSTG_BYTES;
        const uint32_t sB = sA + GA_BYTES;
        const __half* Ab = A + (size_t)row0 * K + kc * 64;
        const __half* Bb = Bt + (size_t)col0 * K + kc * 64;
#pragma unroll
        for (int it = 0; it < 12; it++) {
            const int idx = tid + it * 256;        // 0..3071
            if (idx < 2048) {                      // A: 256 rows x 8 segs
                const int r = idx >> 3;
                const int seg = idx & 7;
                CP_ASYNC16(sA + (uint32_t)r * GROWB + seg * 16,
                           Ab + (size_t)r * K + seg * 8);
            } else {                               // B: 128 rows x 8 segs
                const int j2 = idx - 2048;
                const int r = j2 >> 3;
                const int seg = j2 & 7;
                CP_ASYNC16(sB + (uint32_t)r * GROWB + seg * 16,
                           Bb + (size_t)r * K + seg * 8);
            }
        }
    };

    load_stage(0, 0); CP_COMMIT();
    load_stage(1, 1); CP_COMMIT();

    for (int j = 0; j < nk; j++) {
        CP_WAITG1();                     // chunks 0..j landed (group FIFO arithmetic)
        __syncthreads();                 // all threads' loads visible; chunk j-1 compute done
        if (j + 2 < nk) load_stage((j + 2) % 3, j + 2);   // stage held chunk j-1: safe
        CP_COMMIT();                     // always commit (keeps group counting exact)

        const uint32_t stg = smem_u + (j % 3) * GSTG_BYTES;
        const uint32_t aBase = stg + aOff;
        const uint32_t bBase = stg + bOff;

#pragma unroll
        for (int kk = 0; kk < 4; kk++) {          // 4 x k16
            uint32_t af[4][4];
#pragma unroll
            for (int i = 0; i < 4; i++)
                LDSM_X4(af[i][0], af[i][1], af[i][2], af[i][3],
                        aBase + i * (16 * GROWB) + kk * 32);
#pragma unroll
            for (int pr = 0; pr < 4; pr++) {
                uint32_t b0, b1, b2, b3;
                LDSM_X4(b0, b1, b2, b3, bBase + pr * (16 * GROWB) + kk * 32);
#pragma unroll
                for (int i = 0; i < 4; i++) {
                    mma_f16(acc[i][2 * pr + 0], af[i][0], af[i][1], af[i][2], af[i][3], b0, b1);
                    mma_f16(acc[i][2 * pr + 1], af[i][0], af[i][1], af[i][2], af[i][3], b2, b3);
                }
            }
        }
    }

    // -------- epilogue --------
    const float aeff = (EPI == 0 && col0 >= 1024) ? 1.0f : alpha;
#pragma unroll
    for (int i = 0; i < 4; i++) {
        const int r = row0 + warp_m * 64 + i * 16 + gid;
#pragma unroll
        for (int jn = 0; jn < 8; jn++) {
            const int c = col0 + warp_n * 64 + jn * 8 + 2 * tg;
            const float b0 = bias[c], b1 = bias[c + 1];
#pragma unroll
            for (int half_ = 0; half_ < 2; half_++) {
                const int rr = r + half_ * 8;
                float v0 = acc[i][jn][half_ * 2 + 0] + b0;
                float v1 = acc[i][jn][half_ * 2 + 1] + b1;
                if (EPI == 0) {
                    v0 *= aeff; v1 *= aeff;
                } else if (EPI == 1) {
                    v0 = 0.5f * v0 * (1.0f + erff(v0 * 0.70710678118654752f));
                    v1 = 0.5f * v1 * (1.0f + erff(v1 * 0.70710678118654752f));
                }
                if (EPI == 2) {
                    const uint32_t ru = *reinterpret_cast<const uint32_t*>(Rh + (size_t)rr * N + c);
                    const __half2 rh2 = *reinterpret_cast<const __half2*>(&ru);
                    float* Cf = (float*)Cout;
                    *reinterpret_cast<float2*>(Cf + (size_t)rr * N + c) =
                        make_float2(v0 + __low2float(rh2), v1 + __high2float(rh2));
                } else {
                    __half* Ch = (__half*)Cout;
                    *reinterpret_cast<uint32_t*>(Ch + (size_t)rr * N + c) = packh2(v0, v1);
                }
            }
        }
    }
}

// =====================  flash attention (R14, unchanged)  =====================
static constexpr int ROWB = 144;

__global__ __launch_bounds__(256)
void attn_mma(const float* __restrict__ mask)
{
    const int chunk = blockIdx.x;
    const int h = blockIdx.y;
    const int b = blockIdx.z;
    const int t0 = chunk * 128;
    const int tid = threadIdx.x;
    const int wid = tid >> 5;
    const int lane = tid & 31;
    const int gid = lane >> 2;
    const int tg = lane & 3;

    __shared__ uint32_t Qs2[128 * 36];
    __shared__ uint32_t Ks2[64 * 36];
    __shared__ uint32_t Vs2[64 * 36];
    __shared__ __half   kvh[64];

    const uint32_t qU = smem_to_u32(Qs2);
    const uint32_t kU = smem_to_u32(Ks2);
    const uint32_t vU = smem_to_u32(Vs2);

    const uint32_t aOff = (uint32_t)(wid * 16 + (lane & 15)) * ROWB + (lane >> 4) * 16;
    const uint32_t kOff = (uint32_t)(((lane >> 4) & 1) * 8 + (lane & 7)) * ROWB
                        + ((lane >> 3) & 1) * 16;
    const uint32_t vOff = (uint32_t)(((lane >> 3) & 1) * 8 + (lane & 7)) * ROWB
                        + ((lane >> 4) & 1) * 16;

    // ---- load Q tile ----
    const __half* qbase = g_qkvh + ((size_t)(b * LL + t0)) * QKVN + h * DH;
#pragma unroll
    for (int it = 0; it < 8; it++) {
        const int i = tid + it * 256;
        const int r = i >> 4;
        const int s4 = (i & 15) << 2;
        const uint2 u = *reinterpret_cast<const uint2*>(qbase + (size_t)r * QKVN + s4);
        *reinterpret_cast<uint2*>(&Qs2[r * 36 + (s4 >> 1)]) = u;
    }

    float o[8][4];
#pragma unroll
    for (int jn = 0; jn < 8; jn++)
#pragma unroll
        for (int q = 0; q < 4; q++) o[jn][q] = 0.f;
    float l0 = 0.f, l1 = 0.f;

    const int rowA = wid * 16 + gid;
    const int rowB = rowA + 8;
    const __half* kbase = g_qkvh + ((size_t)(b * LL)) * QKVN + 1024 + h * DH;
    const __half* vbase = g_qkvh + ((size_t)(b * LL)) * QKVN + 2048 + h * DH;
    const uint32_t ONE2 = 0x3C003C00u;

    uint2 rk[4], rv[4];
    __half nkv = __float2half(0.f);

    auto preload = [&](int kb0) {
#pragma unroll
        for (int it = 0; it < 4; it++) {
            const int i = tid + it * 256;
            const int r = i >> 4;
            const int s4 = (i & 15) << 2;
            const int kg = kb0 + r;
            uint2 uk = make_uint2(0u, 0u);
            uint2 uv = make_uint2(0u, 0u);
            if (kg >= 0 && kg < LL) {
                uk = *reinterpret_cast<const uint2*>(kbase + (size_t)kg * QKVN + s4);
                uv = *reinterpret_cast<const uint2*>(vbase + (size_t)kg * QKVN + s4);
            }
            rk[it] = uk;
            rv[it] = uv;
        }
        if (tid < 64) {
            const int kg = kb0 + tid;
            bool ok = (kg >= 0) && (kg < LL);
            if (ok) ok = (mask[b * LL + kg] == 0.0f);
            nkv = ok ? __float2half(1.0f) : __float2half(0.0f);
        }
    };

    preload(t0 - 128);

    for (int kbi = 0; kbi < 6; kbi++) {
        const int kb0 = t0 - 128 + kbi * 64;
        __syncthreads();
#pragma unroll
        for (int it = 0; it < 4; it++) {
            const int i = tid + it * 256;
            const int r = i >> 4;
            const int s4 = (i & 15) << 2;
            *reinterpret_cast<uint2*>(&Ks2[r * 36 + (s4 >> 1)]) = rk[it];
            *reinterpret_cast<uint2*>(&Vs2[r * 36 + (s4 >> 1)]) = rv[it];
        }
        if (tid < 64) kvh[tid] = nkv;
        __syncthreads();

        if (kbi < 5) preload(kb0 + 64);

        if ((kbi == 0 && wid >= 4) || (kbi == 5 && wid < 4)) continue;

        // ---- S = Q @ K^T (log2 units) ----
        float s[8][4];
#pragma unroll
        for (int jn = 0; jn < 8; jn++)
#pragma unroll
            for (int q = 0; q < 4; q++) s[jn][q] = 0.f;
#pragma unroll
        for (int kk4 = 0; kk4 < 4; kk4++) {
            uint32_t a0, a1, a2, a3;
            LDSM_X4(a0, a1, a2, a3, qU + aOff + kk4 * 32);
#pragma unroll
            for (int pr = 0; pr < 4; pr++) {
                uint32_t b0, b1, b2, b3;
                LDSM_X4(b0, b1, b2, b3, kU + kOff + pr * (16 * ROWB) + kk4 * 32);
                mma_f16(s[2 * pr + 0], a0, a1, a2, a3, b0, b1);
                mma_f16(s[2 * pr + 1], a0, a1, a2, a3, b2, b3);
            }
        }

        // ---- p = exp2(s - 4) * valid * band -> registers ----
        const uint32_t* kv2 = reinterpret_cast<const uint32_t*>(kvh);
        const bool lo_edge = (kbi < 2);
        const bool hi_edge = (kbi >= 4);
        uint32_t pA[8], pB[8];
#pragma unroll
        for (int jn = 0; jn < 8; jn++) {
            const uint32_t val2 = kv2[jn * 4 + tg];
            uint32_t pa = hmul2u(ex2h2(packh2(s[jn][0] - 4.f, s[jn][1] - 4.f)), val2);
            uint32_t pb = hmul2u(ex2h2(packh2(s[jn][2] - 4.f, s[jn][3] - 4.f)), val2);
            if (lo_edge || hi_edge) {
                const int c = kbi * 64 + jn * 8 + 2 * tg;
                uint32_t bandA, bandB;
                if (lo_edge) {
                    bandA = (c >= rowA ? 0x3C00u : 0u) | (c + 1 >= rowA ? 0x3C000000u : 0u);
                    bandB = (c >= rowB ? 0x3C00u : 0u) | (c + 1 >= rowB ? 0x3C000000u : 0u);
                } else {
                    bandA = (c <= rowA + 256 ? 0x3C00u : 0u) | (c + 1 <= rowA + 256 ? 0x3C000000u : 0u);
                    bandB = (c <= rowB + 256 ? 0x3C00u : 0u) | (c + 1 <= rowB + 256 ? 0x3C000000u : 0u);
                }
                pa = hmul2u(pa, bandA);
                pb = hmul2u(pb, bandB);
            }
            pA[jn] = pa;
            pB[jn] = pb;
        }

        // ---- O += P @ V ; l += rowsum(P) ----
        float ls[4] = {0.f, 0.f, 0.f, 0.f};
#pragma unroll
        for (int kk4 = 0; kk4 < 4; kk4++) {
            const uint32_t a0 = pA[2 * kk4];
            const uint32_t a1 = pB[2 * kk4];
            const uint32_t a2 = pA[2 * kk4 + 1];
            const uint32_t a3 = pB[2 * kk4 + 1];
            mma_f16(ls, a0, a1, a2, a3, ONE2, ONE2);
#pragma unroll
            for (int pr = 0; pr < 4; pr++) {
                uint32_t b0, b1, b2, b3;
                LDSM_X4_T(b0, b1, b2, b3, vU + vOff + kk4 * (16 * ROWB) + pr * 32);
                mma_f16(o[2 * pr + 0], a0, a1, a2, a3, b0, b1);
                mma_f16(o[2 * pr + 1], a0, a1, a2, a3, b2, b3);
            }
        }
        l0 += ls[0];
        l1 += ls[2];
    }

    const float inv0 = (l0 > 0.f) ? 1.0f / l0 : 0.f;
    const float inv1 = (l1 > 0.f) ? 1.0f / l1 : 0.f;
    __half* oA = g_attnh + ((size_t)(b * LL + t0 + rowA)) * DD + h * DH;
    __half* oB = g_attnh + ((size_t)(b * LL + t0 + rowB)) * DD + h * DH;
#pragma unroll
    for (int jn = 0; jn < 8; jn++) {
        const int c = jn * 8 + 2 * tg;
        *reinterpret_cast<uint32_t*>(oA + c) = packh2(o[jn][0] * inv0, o[jn][1] * inv0);
        *reinterpret_cast<uint32_t*>(oB + c) = packh2(o[jn][2] * inv1, o[jn][3] * inv1);
    }
}

// ---------------- residual + LayerNorm (f16 attn in, f16 out only) ----------------
__global__ __launch_bounds__(256)
void ln_kernel(const float* __restrict__ x, const float* __restrict__ gamma,
               const float* __restrict__ beta)
{
    const int row = blockIdx.x;
    const int tid = threadIdx.x;
    const float* xr = x + (size_t)row * DD;
    const __half* ar = g_attnh + (size_t)row * DD;

    float4 xv = *reinterpret_cast<const float4*>(xr + tid * 4);
    const uint2 au = *reinterpret_cast<const uint2*>(ar + tid * 4);
    const __half2 a01 = *reinterpret_cast<const __half2*>(&au.x);
    const __half2 a23 = *reinterpret_cast<const __half2*>(&au.y);
    float hv[4] = {xv.x + __low2float(a01), xv.y + __high2float(a01),
                   xv.z + __low2float(a23), xv.w + __high2float(a23)};

    float s = hv[0] + hv[1] + hv[2] + hv[3];
    float ss = hv[0] * hv[0] + hv[1] * hv[1] + hv[2] * hv[2] + hv[3] * hv[3];

    __shared__ float red_s[8], red_ss[8];
#pragma unroll
    for (int off = 16; off > 0; off >>= 1) {
        s += __shfl_xor_sync(0xffffffff, s, off);
        ss += __shfl_xor_sync(0xffffffff, ss, off);
    }
    const int warp = tid >> 5;
    if ((tid & 31) == 0) { red_s[warp] = s; red_ss[warp] = ss; }
    __syncthreads();
    if (tid < 32) {
        float a = (tid < 8) ? red_s[tid] : 0.f;
        float c = (tid < 8) ? red_ss[tid] : 0.f;
#pragma unroll
        for (int off = 4; off > 0; off >>= 1) {
            a += __shfl_xor_sync(0xffffffff, a, off);
            c += __shfl_xor_sync(0xffffffff, c, off);
        }
        if (tid == 0) { red_s[0] = a; red_ss[0] = c; }
    }
    __syncthreads();
    const float mean = red_s[0] * (1.0f / DD);
    const float var = red_ss[0] * (1.0f / DD) - mean * mean;
    const float rstd = rsqrtf(var + 1e-5f);

    float4 gv = *reinterpret_cast<const float4*>(gamma + tid * 4);
    float4 bv = *reinterpret_cast<const float4*>(beta + tid * 4);
    float o0 = (hv[0] - mean) * rstd * gv.x + bv.x;
    float o1 = (hv[1] - mean) * rstd * gv.y + bv.y;
    float o2 = (hv[2] - mean) * rstd * gv.z + bv.z;
    float o3 = (hv[3] - mean) * rstd * gv.w + bv.w;
    uint2 u;
    u.x = packh2(o0, o1);
    u.y = packh2(o2, o3);
    *reinterpret_cast<uint2*>(g_hnh + (size_t)row * DD + tid * 4) = u;
}

// ---------------- launch ----------------
extern "C" void kernel_launch(void* const* d_in, const int* in_sizes, int n_in,
                              void* d_out, int out_size)
{
    const float* x    = (const float*)d_in[0];
    const float* mask = (const float*)d_in[1];
    const float* Wq   = (const float*)d_in[2];
    const float* bq   = (const float*)d_in[3];
    const float* Wk   = (const float*)d_in[4];
    const float* bk   = (const float*)d_in[5];
    const float* Wv   = (const float*)d_in[6];
    const float* bv   = (const float*)d_in[7];
    const float* ln_g = (const float*)d_in[8];
    const float* ln_b = (const float*)d_in[9];
    const float* W1   = (const float*)d_in[10];
    const float* b1   = (const float*)d_in[11];
    const float* W2   = (const float*)d_in[12];
    const float* b2   = (const float*)d_in[13];
    float* out = (float*)d_out;

    __half *xh, *qkvh, *hnh, *acth, *wqkvt, *w1t, *w2t;
    float *bqkv;
    cudaGetSymbolAddress((void**)&xh,    g_xh);
    cudaGetSymbolAddress((void**)&qkvh,  g_qkvh);
    cudaGetSymbolAddress((void**)&hnh,   g_hnh);
    cudaGetSymbolAddress((void**)&acth,  g_acth);
    cudaGetSymbolAddress((void**)&wqkvt, g_wqkvt);
    cudaGetSymbolAddress((void**)&bqkv,  g_bqkv);
    cudaGetSymbolAddress((void**)&w1t,   g_w1t);
    cudaGetSymbolAddress((void**)&w2t,   g_w2t);

    cudaFuncSetAttribute(hgemm<0>, cudaFuncAttributeMaxDynamicSharedMemorySize, GEMM_DSMEM);
    cudaFuncSetAttribute(hgemm<1>, cudaFuncAttributeMaxDynamicSharedMemorySize, GEMM_DSMEM);
    cudaFuncSetAttribute(hgemm<2>, cudaFuncAttributeMaxDynamicSharedMemorySize, GEMM_DSMEM);

    // fused preprocessing
    prep_kernel<<<19468, 256>>>(x, Wq, Wk, Wv, W1, W2, bq, bk, bv);

    // fused QKV projection
    hgemm<0><<<dim3(QKVN / 128, ROWS / 256), 256, GEMM_DSMEM>>>(xh, wqkvt, bqkv, nullptr, qkvh, ROWS, QKVN, DD, 0.125f * LOG2E);

    // flash attention
    attn_mma<<<dim3(LL / 128, HH, BB), 256>>>(mask);

    // residual + LayerNorm (f16 out)
    ln_kernel<<<ROWS, 256>>>(x, ln_g, ln_b);

    // MLP
    hgemm<1><<<dim3(FF / 128, ROWS / 256), 256, GEMM_DSMEM>>>(hnh, w1t, b1, nullptr, acth, ROWS, FF, DD, 1.0f);
    hgemm<2><<<dim3(DD / 128, ROWS / 256), 256, GEMM_DSMEM>>>(acth, w2t, b2, hnh, out, ROWS, DD, FF, 1.0f);
}

// round 16
// speedup vs baseline: 1.0268x; 1.0268x over previous
#include <cuda_runtime.h>
#include <cuda_bf16.h>
#include <cuda_fp16.h>
#include <math.h>
#include <stdint.h>

#define BB 2
#define LL 4096
#define DD 1024
#define HH 16
#define DH 64
#define FF 4096
#define ROWS (BB*LL)   // 8192
#define QKVN 3072
#define LOG2E 1.4426950408889634f

// ---------------- scratch ----------------
__device__ __half g_xh[ROWS * DD];
__device__ __half g_qkvh[ROWS * QKVN];   // packed q|k|v per row
__device__ __half g_attnh[ROWS * DD];    // attention out (f16)
__device__ __half g_hnh[ROWS * DD];      // LN out f16 (GEMM operand + residual)
__device__ __half g_acth[ROWS * FF];
__device__ __half g_wqkvt[QKVN * DD];    // [Wq^T ; Wk^T ; Wv^T]
__device__ float  g_bqkv[QKVN];
__device__ __half g_w1t[DD * FF];
__device__ __half g_w2t[FF * DD];

// =====================  helpers  =====================
__device__ __forceinline__ uint32_t smem_to_u32(const void* p) {
    uint32_t a;
    asm("{ .reg .u64 t; cvta.to.shared.u64 t, %1; cvt.u32.u64 %0, t; }" : "=r"(a) : "l"(p));
    return a;
}

#define CP_ASYNC16(dst, src) \
    asm volatile("cp.async.cg.shared.global [%0], [%1], 16;" :: "r"(dst), "l"(src))
#define CP_COMMIT() asm volatile("cp.async.commit_group;" ::: "memory")
#define CP_WAIT1()  asm volatile("cp.async.wait_group 1;" ::: "memory")

#define LDSM_X4(r0, r1, r2, r3, addr) \
    asm volatile("ldmatrix.sync.aligned.m8n8.x4.shared.b16 {%0,%1,%2,%3}, [%4];" \
        : "=r"(r0), "=r"(r1), "=r"(r2), "=r"(r3) : "r"(addr))
#define LDSM_X4_T(r0, r1, r2, r3, addr) \
    asm volatile("ldmatrix.sync.aligned.m8n8.x4.trans.shared.b16 {%0,%1,%2,%3}, [%4];" \
        : "=r"(r0), "=r"(r1), "=r"(r2), "=r"(r3) : "r"(addr))

__device__ __forceinline__ void mma_f16(float* d, uint32_t a0, uint32_t a1,
                                        uint32_t a2, uint32_t a3,
                                        uint32_t b0, uint32_t b1) {
    asm volatile(
        "mma.sync.aligned.m16n8k16.row.col.f32.f16.f16.f32 "
        "{%0,%1,%2,%3}, {%4,%5,%6,%7}, {%8,%9}, {%0,%1,%2,%3};"
        : "+f"(d[0]), "+f"(d[1]), "+f"(d[2]), "+f"(d[3])
        : "r"(a0), "r"(a1), "r"(a2), "r"(a3), "r"(b0), "r"(b1));
}

__device__ __forceinline__ uint32_t ex2h2(uint32_t x) {
    uint32_t r; asm("ex2.approx.f16x2 %0, %1;" : "=r"(r) : "r"(x)); return r;
}
__device__ __forceinline__ uint32_t packh2(float lo, float hi) {
    uint32_t r; asm("cvt.rn.f16x2.f32 %0, %1, %2;" : "=r"(r) : "f"(hi), "f"(lo)); return r;
}
__device__ __forceinline__ uint32_t hmul2u(uint32_t a, uint32_t b) {
    uint32_t r; asm("mul.f16x2 %0, %1, %2;" : "=r"(r) : "r"(a), "r"(b)); return r;
}

// =====================  fused preprocessing kernel (R13)  =====================
__device__ __forceinline__ void transpose_tile(const float* __restrict__ in,
                                               __half* __restrict__ out,
                                               int R, int C, int bx, int by,
                                               float* t, int tid)
{
    const int tx = tid & 31;
    const int ty = tid >> 5;
    const int x = bx * 32 + tx;
#pragma unroll
    for (int i = 0; i < 32; i += 8) {
        const int y = by * 32 + ty + i;
        t[(ty + i) * 33 + tx] = in[(size_t)y * C + x];
    }
    __syncthreads();
    const int x2 = by * 32 + tx;
#pragma unroll
    for (int i = 0; i < 32; i += 8) {
        const int y2 = bx * 32 + ty + i;
        out[(size_t)y2 * R + x2] = __float2half_rn(t[tx * 33 + ty + i]);
    }
}

__global__ __launch_bounds__(256)
void prep_kernel(const float* __restrict__ x,
                 const float* __restrict__ Wq, const float* __restrict__ Wk,
                 const float* __restrict__ Wv, const float* __restrict__ W1,
                 const float* __restrict__ W2,
                 const float* __restrict__ bq, const float* __restrict__ bk,
                 const float* __restrict__ bv)
{
    __shared__ float t[32 * 33];
    const int blk = blockIdx.x;
    const int tid = threadIdx.x;

    if (blk < 8192) {
        const int i = blk * 256 + tid;
        const float4 f = *reinterpret_cast<const float4*>(x + (size_t)i * 4);
        uint2 u;
        u.x = packh2(f.x, f.y);
        u.y = packh2(f.z, f.w);
        *reinterpret_cast<uint2*>(g_xh + (size_t)i * 4) = u;
    } else if (blk < 11264) {
        const int r = blk - 8192;
        const int z = r >> 10;
        const int tI = r & 1023;
        const float* in = (z == 0) ? Wq : (z == 1) ? Wk : Wv;
        transpose_tile(in, g_wqkvt + (size_t)z * DD * DD, DD, DD,
                       tI & 31, tI >> 5, t, tid);
    } else if (blk < 15360) {
        const int r = blk - 11264;
        transpose_tile(W1, g_w1t, DD, FF, r & 127, r >> 7, t, tid);
    } else if (blk < 19456) {
        const int r = blk - 15360;
        transpose_tile(W2, g_w2t, FF, DD, r & 31, r >> 5, t, tid);
    } else {
        const int i = (blk - 19456) * 256 + tid;
        if (i < 1024) g_bqkv[i] = bq[i];
        else if (i < 2048) g_bqkv[i] = bk[i - 1024];
        else if (i < 3072) g_bqkv[i] = bv[i - 2048];
    }
}

// =====================  f16 mma.sync GEMM, 256x128x128 tile, 2-stage (R14, frozen)  =====================
static constexpr int GROWB = 272;
static constexpr int GA_BYTES = 256 * GROWB;
static constexpr int GSTG_BYTES = GA_BYTES + 128 * GROWB;
static constexpr uint32_t GEMM_DSMEM = 2 * GSTG_BYTES;

// EPI 0: *= alpha -> half ; EPI 1: gelu -> half ; EPI 2: += Rh (f16 residual) -> fp32
template<int EPI>
__global__ __launch_bounds__(256, 1)
void hgemm(const __half* __restrict__ A, const __half* __restrict__ Bt,
           const float* __restrict__ bias, const __half* __restrict__ Rh,
           void* __restrict__ Cout, int M, int N, int K, float alpha)
{
    extern __shared__ char dsm[];
    const uint32_t smem_u = smem_to_u32(dsm);
    const int tid = threadIdx.x;
    const int wid = tid >> 5;
    const int lane = tid & 31;
    const int gid = lane >> 2;
    const int tg = lane & 3;
    const int warp_m = wid & 3;
    const int warp_n = wid >> 2;
    const int row0 = blockIdx.y * 256;
    const int col0 = blockIdx.x * 128;
    const int nk = K >> 7;

    float acc[4][8][4];
#pragma unroll
    for (int i = 0; i < 4; i++)
#pragma unroll
        for (int j = 0; j < 8; j++)
#pragma unroll
            for (int q = 0; q < 4; q++) acc[i][j][q] = 0.f;

    const uint32_t aOff = (uint32_t)(warp_m * 64 + (lane & 15)) * GROWB + (lane >> 4) * 16;
    const uint32_t bOff = (uint32_t)GA_BYTES
                        + (uint32_t)(warp_n * 64 + ((lane >> 4) & 1) * 8 + (lane & 7)) * GROWB
                        + ((lane >> 3) & 1) * 16;

    auto load_stage = [&](int s, int kc) {
        const uint32_t sA = smem_u + s * GSTG_BYTES;
        const uint32_t sB = sA + GA_BYTES;
        const __half* Ab = A + (size_t)row0 * K + kc * 128;
        const __half* Bb = Bt + (size_t)col0 * K + kc * 128;
#pragma unroll
        for (int it = 0; it < 24; it++) {
            const int idx = tid + it * 256;
            if (idx < 4096) {
                const int r = idx >> 4;
                const int seg = idx & 15;
                CP_ASYNC16(sA + (uint32_t)r * GROWB + seg * 16,
                           Ab + (size_t)r * K + seg * 8);
            } else {
                const int j2 = idx - 4096;
                const int r = j2 >> 4;
                const int seg = j2 & 15;
                CP_ASYNC16(sB + (uint32_t)r * GROWB + seg * 16,
                           Bb + (size_t)r * K + seg * 8);
            }
        }
    };

    load_stage(0, 0); CP_COMMIT();

    for (int j = 0; j < nk; j++) {
        __syncthreads();
        if (j + 1 < nk) load_stage((j + 1) & 1, j + 1);
        CP_COMMIT();
        CP_WAIT1();
        __syncthreads();

        const uint32_t stg = smem_u + (j & 1) * GSTG_BYTES;
        const uint32_t aBase = stg + aOff;
        const uint32_t bBase = stg + bOff;

#pragma unroll
        for (int kk = 0; kk < 8; kk++) {
            uint32_t af[4][4];
#pragma unroll
            for (int i = 0; i < 4; i++)
                LDSM_X4(af[i][0], af[i][1], af[i][2], af[i][3],
                        aBase + i * (16 * GROWB) + kk * 32);
#pragma unroll
            for (int pr = 0; pr < 4; pr++) {
                uint32_t b0, b1, b2, b3;
                LDSM_X4(b0, b1, b2, b3, bBase + pr * (16 * GROWB) + kk * 32);
#pragma unroll
                for (int i = 0; i < 4; i++) {
                    mma_f16(acc[i][2 * pr + 0], af[i][0], af[i][1], af[i][2], af[i][3], b0, b1);
                    mma_f16(acc[i][2 * pr + 1], af[i][0], af[i][1], af[i][2], af[i][3], b2, b3);
                }
            }
        }
    }

    // -------- epilogue --------
    const float aeff = (EPI == 0 && col0 >= 1024) ? 1.0f : alpha;
#pragma unroll
    for (int i = 0; i < 4; i++) {
        const int r = row0 + warp_m * 64 + i * 16 + gid;
#pragma unroll
        for (int jn = 0; jn < 8; jn++) {
            const int c = col0 + warp_n * 64 + jn * 8 + 2 * tg;
            const float b0 = bias[c], b1 = bias[c + 1];
#pragma unroll
            for (int half_ = 0; half_ < 2; half_++) {
                const int rr = r + half_ * 8;
                float v0 = acc[i][jn][half_ * 2 + 0] + b0;
                float v1 = acc[i][jn][half_ * 2 + 1] + b1;
                if (EPI == 0) {
                    v0 *= aeff; v1 *= aeff;
                } else if (EPI == 1) {
                    v0 = 0.5f * v0 * (1.0f + erff(v0 * 0.70710678118654752f));
                    v1 = 0.5f * v1 * (1.0f + erff(v1 * 0.70710678118654752f));
                }
                if (EPI == 2) {
                    const uint32_t ru = *reinterpret_cast<const uint32_t*>(Rh + (size_t)rr * N + c);
                    const __half2 rh2 = *reinterpret_cast<const __half2*>(&ru);
                    float* Cf = (float*)Cout;
                    *reinterpret_cast<float2*>(Cf + (size_t)rr * N + c) =
                        make_float2(v0 + __low2float(rh2), v1 + __high2float(rh2));
                } else {
                    __half* Ch = (__half*)Cout;
                    *reinterpret_cast<uint32_t*>(Ch + (size_t)rr * N + c) = packh2(v0, v1);
                }
            }
        }
    }
}

// =====================  flash attention (R14, unchanged)  =====================
static constexpr int ROWB = 144;

__global__ __launch_bounds__(256)
void attn_mma(const float* __restrict__ mask)
{
    const int chunk = blockIdx.x;
    const int h = blockIdx.y;
    const int b = blockIdx.z;
    const int t0 = chunk * 128;
    const int tid = threadIdx.x;
    const int wid = tid >> 5;
    const int lane = tid & 31;
    const int gid = lane >> 2;
    const int tg = lane & 3;

    __shared__ uint32_t Qs2[128 * 36];
    __shared__ uint32_t Ks2[64 * 36];
    __shared__ uint32_t Vs2[64 * 36];
    __shared__ __half   kvh[64];

    const uint32_t qU = smem_to_u32(Qs2);
    const uint32_t kU = smem_to_u32(Ks2);
    const uint32_t vU = smem_to_u32(Vs2);

    const uint32_t aOff = (uint32_t)(wid * 16 + (lane & 15)) * ROWB + (lane >> 4) * 16;
    const uint32_t kOff = (uint32_t)(((lane >> 4) & 1) * 8 + (lane & 7)) * ROWB
                        + ((lane >> 3) & 1) * 16;
    const uint32_t vOff = (uint32_t)(((lane >> 3) & 1) * 8 + (lane & 7)) * ROWB
                        + ((lane >> 4) & 1) * 16;

    // ---- load Q tile ----
    const __half* qbase = g_qkvh + ((size_t)(b * LL + t0)) * QKVN + h * DH;
#pragma unroll
    for (int it = 0; it < 8; it++) {
        const int i = tid + it * 256;
        const int r = i >> 4;
        const int s4 = (i & 15) << 2;
        const uint2 u = *reinterpret_cast<const uint2*>(qbase + (size_t)r * QKVN + s4);
        *reinterpret_cast<uint2*>(&Qs2[r * 36 + (s4 >> 1)]) = u;
    }

    float o[8][4];
#pragma unroll
    for (int jn = 0; jn < 8; jn++)
#pragma unroll
        for (int q = 0; q < 4; q++) o[jn][q] = 0.f;
    float l0 = 0.f, l1 = 0.f;

    const int rowA = wid * 16 + gid;
    const int rowB = rowA + 8;
    const __half* kbase = g_qkvh + ((size_t)(b * LL)) * QKVN + 1024 + h * DH;
    const __half* vbase = g_qkvh + ((size_t)(b * LL)) * QKVN + 2048 + h * DH;
    const uint32_t ONE2 = 0x3C003C00u;

    uint2 rk[4], rv[4];
    __half nkv = __float2half(0.f);

    auto preload = [&](int kb0) {
#pragma unroll
        for (int it = 0; it < 4; it++) {
            const int i = tid + it * 256;
            const int r = i >> 4;
            const int s4 = (i & 15) << 2;
            const int kg = kb0 + r;
            uint2 uk = make_uint2(0u, 0u);
            uint2 uv = make_uint2(0u, 0u);
            if (kg >= 0 && kg < LL) {
                uk = *reinterpret_cast<const uint2*>(kbase + (size_t)kg * QKVN + s4);
                uv = *reinterpret_cast<const uint2*>(vbase + (size_t)kg * QKVN + s4);
            }
            rk[it] = uk;
            rv[it] = uv;
        }
        if (tid < 64) {
            const int kg = kb0 + tid;
            bool ok = (kg >= 0) && (kg < LL);
            if (ok) ok = (mask[b * LL + kg] == 0.0f);
            nkv = ok ? __float2half(1.0f) : __float2half(0.0f);
        }
    };

    preload(t0 - 128);

    for (int kbi = 0; kbi < 6; kbi++) {
        const int kb0 = t0 - 128 + kbi * 64;
        __syncthreads();
#pragma unroll
        for (int it = 0; it < 4; it++) {
            const int i = tid + it * 256;
            const int r = i >> 4;
            const int s4 = (i & 15) << 2;
            *reinterpret_cast<uint2*>(&Ks2[r * 36 + (s4 >> 1)]) = rk[it];
            *reinterpret_cast<uint2*>(&Vs2[r * 36 + (s4 >> 1)]) = rv[it];
        }
        if (tid < 64) kvh[tid] = nkv;
        __syncthreads();

        if (kbi < 5) preload(kb0 + 64);

        if ((kbi == 0 && wid >= 4) || (kbi == 5 && wid < 4)) continue;

        // ---- S = Q @ K^T (log2 units) ----
        float s[8][4];
#pragma unroll
        for (int jn = 0; jn < 8; jn++)
#pragma unroll
            for (int q = 0; q < 4; q++) s[jn][q] = 0.f;
#pragma unroll
        for (int kk4 = 0; kk4 < 4; kk4++) {
            uint32_t a0, a1, a2, a3;
            LDSM_X4(a0, a1, a2, a3, qU + aOff + kk4 * 32);
#pragma unroll
            for (int pr = 0; pr < 4; pr++) {
                uint32_t b0, b1, b2, b3;
                LDSM_X4(b0, b1, b2, b3, kU + kOff + pr * (16 * ROWB) + kk4 * 32);
                mma_f16(s[2 * pr + 0], a0, a1, a2, a3, b0, b1);
                mma_f16(s[2 * pr + 1], a0, a1, a2, a3, b2, b3);
            }
        }

        // ---- p = exp2(s - 4) * valid * band -> registers ----
        const uint32_t* kv2 = reinterpret_cast<const uint32_t*>(kvh);
        const bool lo_edge = (kbi < 2);
        const bool hi_edge = (kbi >= 4);
        uint32_t pA[8], pB[8];
#pragma unroll
        for (int jn = 0; jn < 8; jn++) {
            const uint32_t val2 = kv2[jn * 4 + tg];
            uint32_t pa = hmul2u(ex2h2(packh2(s[jn][0] - 4.f, s[jn][1] - 4.f)), val2);
            uint32_t pb = hmul2u(ex2h2(packh2(s[jn][2] - 4.f, s[jn][3] - 4.f)), val2);
            if (lo_edge || hi_edge) {
                const int c = kbi * 64 + jn * 8 + 2 * tg;
                uint32_t bandA, bandB;
                if (lo_edge) {
                    bandA = (c >= rowA ? 0x3C00u : 0u) | (c + 1 >= rowA ? 0x3C000000u : 0u);
                    bandB = (c >= rowB ? 0x3C00u : 0u) | (c + 1 >= rowB ? 0x3C000000u : 0u);
                } else {
                    bandA = (c <= rowA + 256 ? 0x3C00u : 0u) | (c + 1 <= rowA + 256 ? 0x3C000000u : 0u);
                    bandB = (c <= rowB + 256 ? 0x3C00u : 0u) | (c + 1 <= rowB + 256 ? 0x3C000000u : 0u);
                }
                pa = hmul2u(pa, bandA);
                pb = hmul2u(pb, bandB);
            }
            pA[jn] = pa;
            pB[jn] = pb;
        }

        // ---- O += P @ V ; l += rowsum(P) ----
        float ls[4] = {0.f, 0.f, 0.f, 0.f};
#pragma unroll
        for (int kk4 = 0; kk4 < 4; kk4++) {
            const uint32_t a0 = pA[2 * kk4];
            const uint32_t a1 = pB[2 * kk4];
            const uint32_t a2 = pA[2 * kk4 + 1];
            const uint32_t a3 = pB[2 * kk4 + 1];
            mma_f16(ls, a0, a1, a2, a3, ONE2, ONE2);
#pragma unroll
            for (int pr = 0; pr < 4; pr++) {
                uint32_t b0, b1, b2, b3;
                LDSM_X4_T(b0, b1, b2, b3, vU + vOff + kk4 * (16 * ROWB) + pr * 32);
                mma_f16(o[2 * pr + 0], a0, a1, a2, a3, b0, b1);
                mma_f16(o[2 * pr + 1], a0, a1, a2, a3, b2, b3);
            }
        }
        l0 += ls[0];
        l1 += ls[2];
    }

    const float inv0 = (l0 > 0.f) ? 1.0f / l0 : 0.f;
    const float inv1 = (l1 > 0.f) ? 1.0f / l1 : 0.f;
    __half* oA = g_attnh + ((size_t)(b * LL + t0 + rowA)) * DD + h * DH;
    __half* oB = g_attnh + ((size_t)(b * LL + t0 + rowB)) * DD + h * DH;
#pragma unroll
    for (int jn = 0; jn < 8; jn++) {
        const int c = jn * 8 + 2 * tg;
        *reinterpret_cast<uint32_t*>(oA + c) = packh2(o[jn][0] * inv0, o[jn][1] * inv0);
        *reinterpret_cast<uint32_t*>(oB + c) = packh2(o[jn][2] * inv1, o[jn][3] * inv1);
    }
}

// ---------------- residual + LayerNorm (f16 x + f16 attn in, f16 out) ----------------
__global__ __launch_bounds__(256)
void ln_kernel(const float* __restrict__ gamma, const float* __restrict__ beta)
{
    const int row = blockIdx.x;
    const int tid = threadIdx.x;
    const __half* xr = g_xh + (size_t)row * DD;
    const __half* ar = g_attnh + (size_t)row * DD;

    const uint2 xu = *reinterpret_cast<const uint2*>(xr + tid * 4);
    const uint2 au = *reinterpret_cast<const uint2*>(ar + tid * 4);
    const __half2 x01 = *reinterpret_cast<const __half2*>(&xu.x);
    const __half2 x23 = *reinterpret_cast<const __half2*>(&xu.y);
    const __half2 a01 = *reinterpret_cast<const __half2*>(&au.x);
    const __half2 a23 = *reinterpret_cast<const __half2*>(&au.y);
    float hv[4] = {__low2float(x01) + __low2float(a01),
                   __high2float(x01) + __high2float(a01),
                   __low2float(x23) + __low2float(a23),
                   __high2float(x23) + __high2float(a23)};

    float s = hv[0] + hv[1] + hv[2] + hv[3];
    float ss = hv[0] * hv[0] + hv[1] * hv[1] + hv[2] * hv[2] + hv[3] * hv[3];

    __shared__ float red_s[8], red_ss[8];
#pragma unroll
    for (int off = 16; off > 0; off >>= 1) {
        s += __shfl_xor_sync(0xffffffff, s, off);
        ss += __shfl_xor_sync(0xffffffff, ss, off);
    }
    const int warp = tid >> 5;
    if ((tid & 31) == 0) { red_s[warp] = s; red_ss[warp] = ss; }
    __syncthreads();
    if (tid < 32) {
        float a = (tid < 8) ? red_s[tid] : 0.f;
        float c = (tid < 8) ? red_ss[tid] : 0.f;
#pragma unroll
        for (int off = 4; off > 0; off >>= 1) {
            a += __shfl_xor_sync(0xffffffff, a, off);
            c += __shfl_xor_sync(0xffffffff, c, off);
        }
        if (tid == 0) { red_s[0] = a; red_ss[0] = c; }
    }
    __syncthreads();
    const float mean = red_s[0] * (1.0f / DD);
    const float var = red_ss[0] * (1.0f / DD) - mean * mean;
    const float rstd = rsqrtf(var + 1e-5f);

    float4 gv = *reinterpret_cast<const float4*>(gamma + tid * 4);
    float4 bv = *reinterpret_cast<const float4*>(beta + tid * 4);
    float o0 = (hv[0] - mean) * rstd * gv.x + bv.x;
    float o1 = (hv[1] - mean) * rstd * gv.y + bv.y;
    float o2 = (hv[2] - mean) * rstd * gv.z + bv.z;
    float o3 = (hv[3] - mean) * rstd * gv.w + bv.w;
    uint2 u;
    u.x = packh2(o0, o1);
    u.y = packh2(o2, o3);
    *reinterpret_cast<uint2*>(g_hnh + (size_t)row * DD + tid * 4) = u;
}

// ---------------- launch ----------------
extern "C" void kernel_launch(void* const* d_in, const int* in_sizes, int n_in,
                              void* d_out, int out_size)
{
    const float* x    = (const float*)d_in[0];
    const float* mask = (const float*)d_in[1];
    const float* Wq   = (const float*)d_in[2];
    const float* bq   = (const float*)d_in[3];
    const float* Wk   = (const float*)d_in[4];
    const float* bk   = (const float*)d_in[5];
    const float* Wv   = (const float*)d_in[6];
    const float* bv   = (const float*)d_in[7];
    const float* ln_g = (const float*)d_in[8];
    const float* ln_b = (const float*)d_in[9];
    const float* W1   = (const float*)d_in[10];
    const float* b1   = (const float*)d_in[11];
    const float* W2   = (const float*)d_in[12];
    const float* b2   = (const float*)d_in[13];
    float* out = (float*)d_out;

    __half *xh, *qkvh, *hnh, *acth, *wqkvt, *w1t, *w2t;
    float *bqkv;
    cudaGetSymbolAddress((void**)&xh,    g_xh);
    cudaGetSymbolAddress((void**)&qkvh,  g_qkvh);
    cudaGetSymbolAddress((void**)&hnh,   g_hnh);
    cudaGetSymbolAddress((void**)&acth,  g_acth);
    cudaGetSymbolAddress((void**)&wqkvt, g_wqkvt);
    cudaGetSymbolAddress((void**)&bqkv,  g_bqkv);
    cudaGetSymbolAddress((void**)&w1t,   g_w1t);
    cudaGetSymbolAddress((void**)&w2t,   g_w2t);

    cudaFuncSetAttribute(hgemm<0>, cudaFuncAttributeMaxDynamicSharedMemorySize, GEMM_DSMEM);
    cudaFuncSetAttribute(hgemm<1>, cudaFuncAttributeMaxDynamicSharedMemorySize, GEMM_DSMEM);
    cudaFuncSetAttribute(hgemm<2>, cudaFuncAttributeMaxDynamicSharedMemorySize, GEMM_DSMEM);

    // fused preprocessing
    prep_kernel<<<19468, 256>>>(x, Wq, Wk, Wv, W1, W2, bq, bk, bv);

    // fused QKV projection
    hgemm<0><<<dim3(QKVN / 128, ROWS / 256), 256, GEMM_DSMEM>>>(xh, wqkvt, bqkv, nullptr, qkvh, ROWS, QKVN, DD, 0.125f * LOG2E);

    // flash attention
    attn_mma<<<dim3(LL / 128, HH, BB), 256>>>(mask);

    // residual + LayerNorm (f16 in/out)
    ln_kernel<<<ROWS, 256>>>(ln_g, ln_b);

    // MLP
    hgemm<1><<<dim3(FF / 128, ROWS / 256), 256, GEMM_DSMEM>>>(hnh, w1t, b1, nullptr, acth, ROWS, FF, DD, 1.0f);
    hgemm<2><<<dim3(DD / 128, ROWS / 256), 256, GEMM_DSMEM>>>(acth, w2t, b2, hnh, out, ROWS, DD, FF, 1.0f);
}

// round 17
// speedup vs baseline: 1.0333x; 1.0063x over previous
#include <cuda_runtime.h>
#include <cuda_bf16.h>
#include <cuda_fp16.h>
#include <math.h>
#include <stdint.h>

#define BB 2
#define LL 4096
#define DD 1024
#define HH 16
#define DH 64
#define FF 4096
#define ROWS (BB*LL)   // 8192
#define QKVN 3072
#define LOG2E 1.4426950408889634f

// ---------------- scratch ----------------
__device__ __half g_xh[ROWS * DD];
__device__ __half g_qkvh[ROWS * QKVN];   // packed q|k|v per row
__device__ __half g_attnh[ROWS * DD];    // attention out (f16)
__device__ __half g_hnh[ROWS * DD];      // LN out f16 (GEMM operand + residual)
__device__ __half g_acth[ROWS * FF];
__device__ __half g_wqkvt[QKVN * DD];    // [Wq^T ; Wk^T ; Wv^T]
__device__ float  g_bqkv[QKVN];
__device__ __half g_w1t[DD * FF];
__device__ __half g_w2t[FF * DD];

// =====================  helpers  =====================
__device__ __forceinline__ uint32_t smem_to_u32(const void* p) {
    uint32_t a;
    asm("{ .reg .u64 t; cvta.to.shared.u64 t, %1; cvt.u32.u64 %0, t; }" : "=r"(a) : "l"(p));
    return a;
}

#define CP_ASYNC16(dst, src) \
    asm volatile("cp.async.cg.shared.global [%0], [%1], 16;" :: "r"(dst), "l"(src))
#define CP_COMMIT() asm volatile("cp.async.commit_group;" ::: "memory")
#define CP_WAIT1()  asm volatile("cp.async.wait_group 1;" ::: "memory")

#define LDSM_X4(r0, r1, r2, r3, addr) \
    asm volatile("ldmatrix.sync.aligned.m8n8.x4.shared.b16 {%0,%1,%2,%3}, [%4];" \
        : "=r"(r0), "=r"(r1), "=r"(r2), "=r"(r3) : "r"(addr))
#define LDSM_X4_T(r0, r1, r2, r3, addr) \
    asm volatile("ldmatrix.sync.aligned.m8n8.x4.trans.shared.b16 {%0,%1,%2,%3}, [%4];" \
        : "=r"(r0), "=r"(r1), "=r"(r2), "=r"(r3) : "r"(addr))

__device__ __forceinline__ void mma_f16(float* d, uint32_t a0, uint32_t a1,
                                        uint32_t a2, uint32_t a3,
                                        uint32_t b0, uint32_t b1) {
    asm volatile(
        "mma.sync.aligned.m16n8k16.row.col.f32.f16.f16.f32 "
        "{%0,%1,%2,%3}, {%4,%5,%6,%7}, {%8,%9}, {%0,%1,%2,%3};"
        : "+f"(d[0]), "+f"(d[1]), "+f"(d[2]), "+f"(d[3])
        : "r"(a0), "r"(a1), "r"(a2), "r"(a3), "r"(b0), "r"(b1));
}

__device__ __forceinline__ uint32_t ex2h2(uint32_t x) {
    uint32_t r; asm("ex2.approx.f16x2 %0, %1;" : "=r"(r) : "r"(x)); return r;
}
__device__ __forceinline__ uint32_t packh2(float lo, float hi) {
    uint32_t r; asm("cvt.rn.f16x2.f32 %0, %1, %2;" : "=r"(r) : "f"(hi), "f"(lo)); return r;
}
__device__ __forceinline__ uint32_t hmul2u(uint32_t a, uint32_t b) {
    uint32_t r; asm("mul.f16x2 %0, %1, %2;" : "=r"(r) : "r"(a), "r"(b)); return r;
}

// =====================  fused preprocessing kernel (R13)  =====================
__device__ __forceinline__ void transpose_tile(const float* __restrict__ in,
                                               __half* __restrict__ out,
                                               int R, int C, int bx, int by,
                                               float* t, int tid)
{
    const int tx = tid & 31;
    const int ty = tid >> 5;
    const int x = bx * 32 + tx;
#pragma unroll
    for (int i = 0; i < 32; i += 8) {
        const int y = by * 32 + ty + i;
        t[(ty + i) * 33 + tx] = in[(size_t)y * C + x];
    }
    __syncthreads();
    const int x2 = by * 32 + tx;
#pragma unroll
    for (int i = 0; i < 32; i += 8) {
        const int y2 = bx * 32 + ty + i;
        out[(size_t)y2 * R + x2] = __float2half_rn(t[tx * 33 + ty + i]);
    }
}

__global__ __launch_bounds__(256)
void prep_kernel(const float* __restrict__ x,
                 const float* __restrict__ Wq, const float* __restrict__ Wk,
                 const float* __restrict__ Wv, const float* __restrict__ W1,
                 const float* __restrict__ W2,
                 const float* __restrict__ bq, const float* __restrict__ bk,
                 const float* __restrict__ bv)
{
    __shared__ float t[32 * 33];
    const int blk = blockIdx.x;
    const int tid = threadIdx.x;

    if (blk < 8192) {
        const int i = blk * 256 + tid;
        const float4 f = *reinterpret_cast<const float4*>(x + (size_t)i * 4);
        uint2 u;
        u.x = packh2(f.x, f.y);
        u.y = packh2(f.z, f.w);
        *reinterpret_cast<uint2*>(g_xh + (size_t)i * 4) = u;
    } else if (blk < 11264) {
        const int r = blk - 8192;
        const int z = r >> 10;
        const int tI = r & 1023;
        const float* in = (z == 0) ? Wq : (z == 1) ? Wk : Wv;
        transpose_tile(in, g_wqkvt + (size_t)z * DD * DD, DD, DD,
                       tI & 31, tI >> 5, t, tid);
    } else if (blk < 15360) {
        const int r = blk - 11264;
        transpose_tile(W1, g_w1t, DD, FF, r & 127, r >> 7, t, tid);
    } else if (blk < 19456) {
        const int r = blk - 15360;
        transpose_tile(W2, g_w2t, FF, DD, r & 31, r >> 5, t, tid);
    } else {
        const int i = (blk - 19456) * 256 + tid;
        if (i < 1024) g_bqkv[i] = bq[i];
        else if (i < 2048) g_bqkv[i] = bk[i - 1024];
        else if (i < 3072) g_bqkv[i] = bv[i - 2048];
    }
}

// =====================  f16 mma.sync GEMM, 256x128x128 tile, 2-stage (frozen)  =====================
static constexpr int GROWB = 272;
static constexpr int GA_BYTES = 256 * GROWB;
static constexpr int GSTG_BYTES = GA_BYTES + 128 * GROWB;
static constexpr uint32_t GEMM_DSMEM = 2 * GSTG_BYTES;

// EPI 0: *= alpha -> half ; EPI 1: gelu -> half ; EPI 2: += Rh (f16 residual) -> fp32
template<int EPI>
__global__ __launch_bounds__(256, 1)
void hgemm(const __half* __restrict__ A, const __half* __restrict__ Bt,
           const float* __restrict__ bias, const __half* __restrict__ Rh,
           void* __restrict__ Cout, int M, int N, int K, float alpha)
{
    extern __shared__ char dsm[];
    const uint32_t smem_u = smem_to_u32(dsm);
    const int tid = threadIdx.x;
    const int wid = tid >> 5;
    const int lane = tid & 31;
    const int gid = lane >> 2;
    const int tg = lane & 3;
    const int warp_m = wid & 3;
    const int warp_n = wid >> 2;
    const int row0 = blockIdx.y * 256;
    const int col0 = blockIdx.x * 128;
    const int nk = K >> 7;

    float acc[4][8][4];
#pragma unroll
    for (int i = 0; i < 4; i++)
#pragma unroll
        for (int j = 0; j < 8; j++)
#pragma unroll
            for (int q = 0; q < 4; q++) acc[i][j][q] = 0.f;

    const uint32_t aOff = (uint32_t)(warp_m * 64 + (lane & 15)) * GROWB + (lane >> 4) * 16;
    const uint32_t bOff = (uint32_t)GA_BYTES
                        + (uint32_t)(warp_n * 64 + ((lane >> 4) & 1) * 8 + (lane & 7)) * GROWB
                        + ((lane >> 3) & 1) * 16;

    auto load_stage = [&](int s, int kc) {
        const uint32_t sA = smem_u + s * GSTG_BYTES;
        const uint32_t sB = sA + GA_BYTES;
        const __half* Ab = A + (size_t)row0 * K + kc * 128;
        const __half* Bb = Bt + (size_t)col0 * K + kc * 128;
#pragma unroll
        for (int it = 0; it < 24; it++) {
            const int idx = tid + it * 256;
            if (idx < 4096) {
                const int r = idx >> 4;
                const int seg = idx & 15;
                CP_ASYNC16(sA + (uint32_t)r * GROWB + seg * 16,
                           Ab + (size_t)r * K + seg * 8);
            } else {
                const int j2 = idx - 4096;
                const int r = j2 >> 4;
                const int seg = j2 & 15;
                CP_ASYNC16(sB + (uint32_t)r * GROWB + seg * 16,
                           Bb + (size_t)r * K + seg * 8);
            }
        }
    };

    load_stage(0, 0); CP_COMMIT();

    for (int j = 0; j < nk; j++) {
        __syncthreads();
        if (j + 1 < nk) load_stage((j + 1) & 1, j + 1);
        CP_COMMIT();
        CP_WAIT1();
        __syncthreads();

        const uint32_t stg = smem_u + (j & 1) * GSTG_BYTES;
        const uint32_t aBase = stg + aOff;
        const uint32_t bBase = stg + bOff;

#pragma unroll
        for (int kk = 0; kk < 8; kk++) {
            uint32_t af[4][4];
#pragma unroll
            for (int i = 0; i < 4; i++)
                LDSM_X4(af[i][0], af[i][1], af[i][2], af[i][3],
                        aBase + i * (16 * GROWB) + kk * 32);
#pragma unroll
            for (int pr = 0; pr < 4; pr++) {
                uint32_t b0, b1, b2, b3;
                LDSM_X4(b0, b1, b2, b3, bBase + pr * (16 * GROWB) + kk * 32);
#pragma unroll
                for (int i = 0; i < 4; i++) {
                    mma_f16(acc[i][2 * pr + 0], af[i][0], af[i][1], af[i][2], af[i][3], b0, b1);
                    mma_f16(acc[i][2 * pr + 1], af[i][0], af[i][1], af[i][2], af[i][3], b2, b3);
                }
            }
        }
    }

    // -------- epilogue --------
    const float aeff = (EPI == 0 && col0 >= 1024) ? 1.0f : alpha;
#pragma unroll
    for (int i = 0; i < 4; i++) {
        const int r = row0 + warp_m * 64 + i * 16 + gid;
#pragma unroll
        for (int jn = 0; jn < 8; jn++) {
            const int c = col0 + warp_n * 64 + jn * 8 + 2 * tg;
            const float b0 = bias[c], b1 = bias[c + 1];
#pragma unroll
            for (int half_ = 0; half_ < 2; half_++) {
                const int rr = r + half_ * 8;
                float v0 = acc[i][jn][half_ * 2 + 0] + b0;
                float v1 = acc[i][jn][half_ * 2 + 1] + b1;
                if (EPI == 0) {
                    v0 *= aeff; v1 *= aeff;
                } else if (EPI == 1) {
                    v0 = 0.5f * v0 * (1.0f + erff(v0 * 0.70710678118654752f));
                    v1 = 0.5f * v1 * (1.0f + erff(v1 * 0.70710678118654752f));
                }
                if (EPI == 2) {
                    const uint32_t ru = *reinterpret_cast<const uint32_t*>(Rh + (size_t)rr * N + c);
                    const __half2 rh2 = *reinterpret_cast<const __half2*>(&ru);
                    float* Cf = (float*)Cout;
                    *reinterpret_cast<float2*>(Cf + (size_t)rr * N + c) =
                        make_float2(v0 + __low2float(rh2), v1 + __high2float(rh2));
                } else {
                    __half* Ch = (__half*)Cout;
                    *reinterpret_cast<uint32_t*>(Ch + (size_t)rr * N + c) = packh2(v0, v1);
                }
            }
        }
    }
}

// =====================  flash attention (R14 core, occupancy 2)  =====================
static constexpr int ROWB = 144;

__global__ __launch_bounds__(256, 2)
void attn_mma(const float* __restrict__ mask)
{
    const int chunk = blockIdx.x;
    const int h = blockIdx.y;
    const int b = blockIdx.z;
    const int t0 = chunk * 128;
    const int tid = threadIdx.x;
    const int wid = tid >> 5;
    const int lane = tid & 31;
    const int gid = lane >> 2;
    const int tg = lane & 3;

    __shared__ uint32_t Qs2[128 * 36];
    __shared__ uint32_t Ks2[64 * 36];
    __shared__ uint32_t Vs2[64 * 36];
    __shared__ __half   kvh[64];

    const uint32_t qU = smem_to_u32(Qs2);
    const uint32_t kU = smem_to_u32(Ks2);
    const uint32_t vU = smem_to_u32(Vs2);

    const uint32_t aOff = (uint32_t)(wid * 16 + (lane & 15)) * ROWB + (lane >> 4) * 16;
    const uint32_t kOff = (uint32_t)(((lane >> 4) & 1) * 8 + (lane & 7)) * ROWB
                        + ((lane >> 3) & 1) * 16;
    const uint32_t vOff = (uint32_t)(((lane >> 3) & 1) * 8 + (lane & 7)) * ROWB
                        + ((lane >> 4) & 1) * 16;

    // ---- load Q tile ----
    const __half* qbase = g_qkvh + ((size_t)(b * LL + t0)) * QKVN + h * DH;
#pragma unroll
    for (int it = 0; it < 8; it++) {
        const int i = tid + it * 256;
        const int r = i >> 4;
        const int s4 = (i & 15) << 2;
        const uint2 u = *reinterpret_cast<const uint2*>(qbase + (size_t)r * QKVN + s4);
        *reinterpret_cast<uint2*>(&Qs2[r * 36 + (s4 >> 1)]) = u;
    }

    float o[8][4];
#pragma unroll
    for (int jn = 0; jn < 8; jn++)
#pragma unroll
        for (int q = 0; q < 4; q++) o[jn][q] = 0.f;
    float l0 = 0.f, l1 = 0.f;

    const int rowA = wid * 16 + gid;
    const int rowB = rowA + 8;
    const __half* kbase = g_qkvh + ((size_t)(b * LL)) * QKVN + 1024 + h * DH;
    const __half* vbase = g_qkvh + ((size_t)(b * LL)) * QKVN + 2048 + h * DH;
    const uint32_t ONE2 = 0x3C003C00u;

    uint2 rk[4], rv[4];
    __half nkv = __float2half(0.f);

    auto preload = [&](int kb0) {
#pragma unroll
        for (int it = 0; it < 4; it++) {
            const int i = tid + it * 256;
            const int r = i >> 4;
            const int s4 = (i & 15) << 2;
            const int kg = kb0 + r;
            uint2 uk = make_uint2(0u, 0u);
            uint2 uv = make_uint2(0u, 0u);
            if (kg >= 0 && kg < LL) {
                uk = *reinterpret_cast<const uint2*>(kbase + (size_t)kg * QKVN + s4);
                uv = *reinterpret_cast<const uint2*>(vbase + (size_t)kg * QKVN + s4);
            }
            rk[it] = uk;
            rv[it] = uv;
        }
        if (tid < 64) {
            const int kg = kb0 + tid;
            bool ok = (kg >= 0) && (kg < LL);
            if (ok) ok = (mask[b * LL + kg] == 0.0f);
            nkv = ok ? __float2half(1.0f) : __float2half(0.0f);
        }
    };

    preload(t0 - 128);

    for (int kbi = 0; kbi < 6; kbi++) {
        const int kb0 = t0 - 128 + kbi * 64;
        __syncthreads();
#pragma unroll
        for (int it = 0; it < 4; it++) {
            const int i = tid + it * 256;
            const int r = i >> 4;
            const int s4 = (i & 15) << 2;
            *reinterpret_cast<uint2*>(&Ks2[r * 36 + (s4 >> 1)]) = rk[it];
            *reinterpret_cast<uint2*>(&Vs2[r * 36 + (s4 >> 1)]) = rv[it];
        }
        if (tid < 64) kvh[tid] = nkv;
        __syncthreads();

        if (kbi < 5) preload(kb0 + 64);

        if ((kbi == 0 && wid >= 4) || (kbi == 5 && wid < 4)) continue;

        // ---- S = Q @ K^T (log2 units) ----
        float s[8][4];
#pragma unroll
        for (int jn = 0; jn < 8; jn++)
#pragma unroll
            for (int q = 0; q < 4; q++) s[jn][q] = 0.f;
#pragma unroll
        for (int kk4 = 0; kk4 < 4; kk4++) {
            uint32_t a0, a1, a2, a3;
            LDSM_X4(a0, a1, a2, a3, qU + aOff + kk4 * 32);
#pragma unroll
            for (int pr = 0; pr < 4; pr++) {
                uint32_t b0, b1, b2, b3;
                LDSM_X4(b0, b1, b2, b3, kU + kOff + pr * (16 * ROWB) + kk4 * 32);
                mma_f16(s[2 * pr + 0], a0, a1, a2, a3, b0, b1);
                mma_f16(s[2 * pr + 1], a0, a1, a2, a3, b2, b3);
            }
        }

        // ---- p = exp2(s - 4) * valid * band -> registers ----
        const uint32_t* kv2 = reinterpret_cast<const uint32_t*>(kvh);
        const bool lo_edge = (kbi < 2);
        const bool hi_edge = (kbi >= 4);
        uint32_t pA[8], pB[8];
#pragma unroll
        for (int jn = 0; jn < 8; jn++) {
            const uint32_t val2 = kv2[jn * 4 + tg];
            uint32_t pa = hmul2u(ex2h2(packh2(s[jn][0] - 4.f, s[jn][1] - 4.f)), val2);
            uint32_t pb = hmul2u(ex2h2(packh2(s[jn][2] - 4.f, s[jn][3] - 4.f)), val2);
            if (lo_edge || hi_edge) {
                const int c = kbi * 64 + jn * 8 + 2 * tg;
                uint32_t bandA, bandB;
                if (lo_edge) {
                    bandA = (c >= rowA ? 0x3C00u : 0u) | (c + 1 >= rowA ? 0x3C000000u : 0u);
                    bandB = (c >= rowB ? 0x3C00u : 0u) | (c + 1 >= rowB ? 0x3C000000u : 0u);
                } else {
                    bandA = (c <= rowA + 256 ? 0x3C00u : 0u) | (c + 1 <= rowA + 256 ? 0x3C000000u : 0u);
                    bandB = (c <= rowB + 256 ? 0x3C00u : 0u) | (c + 1 <= rowB + 256 ? 0x3C000000u : 0u);
                }
                pa = hmul2u(pa, bandA);
                pb = hmul2u(pb, bandB);
            }
            pA[jn] = pa;
            pB[jn] = pb;
        }

        // ---- O += P @ V ; l += rowsum(P) ----
        float ls[4] = {0.f, 0.f, 0.f, 0.f};
#pragma unroll
        for (int kk4 = 0; kk4 < 4; kk4++) {
            const uint32_t a0 = pA[2 * kk4];
            const uint32_t a1 = pB[2 * kk4];
            const uint32_t a2 = pA[2 * kk4 + 1];
            const uint32_t a3 = pB[2 * kk4 + 1];
            mma_f16(ls, a0, a1, a2, a3, ONE2, ONE2);
#pragma unroll
            for (int pr = 0; pr < 4; pr++) {
                uint32_t b0, b1, b2, b3;
                LDSM_X4_T(b0, b1, b2, b3, vU + vOff + kk4 * (16 * ROWB) + pr * 32);
                mma_f16(o[2 * pr + 0], a0, a1, a2, a3, b0, b1);
                mma_f16(o[2 * pr + 1], a0, a1, a2, a3, b2, b3);
            }
        }
        l0 += ls[0];
        l1 += ls[2];
    }

    const float inv0 = (l0 > 0.f) ? 1.0f / l0 : 0.f;
    const float inv1 = (l1 > 0.f) ? 1.0f / l1 : 0.f;
    __half* oA = g_attnh + ((size_t)(b * LL + t0 + rowA)) * DD + h * DH;
    __half* oB = g_attnh + ((size_t)(b * LL + t0 + rowB)) * DD + h * DH;
#pragma unroll
    for (int jn = 0; jn < 8; jn++) {
        const int c = jn * 8 + 2 * tg;
        *reinterpret_cast<uint32_t*>(oA + c) = packh2(o[jn][0] * inv0, o[jn][1] * inv0);
        *reinterpret_cast<uint32_t*>(oB + c) = packh2(o[jn][2] * inv1, o[jn][3] * inv1);
    }
}

// ---------------- residual + LayerNorm: warp-per-row, shuffle-only reduce ----------------
__global__ __launch_bounds__(256)
void ln_kernel(const float* __restrict__ gamma, const float* __restrict__ beta)
{
    const int warp = threadIdx.x >> 5;
    const int lane = threadIdx.x & 31;
    const int row = blockIdx.x * 8 + warp;

    const __half* xr = g_xh + (size_t)row * DD;
    const __half* ar = g_attnh + (size_t)row * DD;

    float hv[8][4];
    float s = 0.f, ss = 0.f;
#pragma unroll
    for (int seg = 0; seg < 8; seg++) {
        const int e = seg * 128 + lane * 4;
        const uint2 xu = *reinterpret_cast<const uint2*>(xr + e);
        const uint2 au = *reinterpret_cast<const uint2*>(ar + e);
        const __half2 x01 = *reinterpret_cast<const __half2*>(&xu.x);
        const __half2 x23 = *reinterpret_cast<const __half2*>(&xu.y);
        const __half2 a01 = *reinterpret_cast<const __half2*>(&au.x);
        const __half2 a23 = *reinterpret_cast<const __half2*>(&au.y);
        hv[seg][0] = __low2float(x01) + __low2float(a01);
        hv[seg][1] = __high2float(x01) + __high2float(a01);
        hv[seg][2] = __low2float(x23) + __low2float(a23);
        hv[seg][3] = __high2float(x23) + __high2float(a23);
#pragma unroll
        for (int q = 0; q < 4; q++) {
            s += hv[seg][q];
            ss += hv[seg][q] * hv[seg][q];
        }
    }

#pragma unroll
    for (int off = 16; off > 0; off >>= 1) {
        s += __shfl_xor_sync(0xffffffffu, s, off);
        ss += __shfl_xor_sync(0xffffffffu, ss, off);
    }
    const float mean = s * (1.0f / DD);
    const float var = ss * (1.0f / DD) - mean * mean;
    const float rstd = rsqrtf(var + 1e-5f);

    __half* outp = g_hnh + (size_t)row * DD;
#pragma unroll
    for (int seg = 0; seg < 8; seg++) {
        const int e = seg * 128 + lane * 4;
        const float4 gv = *reinterpret_cast<const float4*>(gamma + e);
        const float4 bv = *reinterpret_cast<const float4*>(beta + e);
        uint2 u;
        u.x = packh2((hv[seg][0] - mean) * rstd * gv.x + bv.x,
                     (hv[seg][1] - mean) * rstd * gv.y + bv.y);
        u.y = packh2((hv[seg][2] - mean) * rstd * gv.z + bv.z,
                     (hv[seg][3] - mean) * rstd * gv.w + bv.w);
        *reinterpret_cast<uint2*>(outp + e) = u;
    }
}

// ---------------- launch ----------------
extern "C" void kernel_launch(void* const* d_in, const int* in_sizes, int n_in,
                              void* d_out, int out_size)
{
    const float* x    = (const float*)d_in[0];
    const float* mask = (const float*)d_in[1];
    const float* Wq   = (const float*)d_in[2];
    const float* bq   = (const float*)d_in[3];
    const float* Wk   = (const float*)d_in[4];
    const float* bk   = (const float*)d_in[5];
    const float* Wv   = (const float*)d_in[6];
    const float* bv   = (const float*)d_in[7];
    const float* ln_g = (const float*)d_in[8];
    const float* ln_b = (const float*)d_in[9];
    const float* W1   = (const float*)d_in[10];
    const float* b1   = (const float*)d_in[11];
    const float* W2   = (const float*)d_in[12];
    const float* b2   = (const float*)d_in[13];
    float* out = (float*)d_out;

    __half *xh, *qkvh, *hnh, *acth, *wqkvt, *w1t, *w2t;
    float *bqkv;
    cudaGetSymbolAddress((void**)&xh,    g_xh);
    cudaGetSymbolAddress((void**)&qkvh,  g_qkvh);
    cudaGetSymbolAddress((void**)&hnh,   g_hnh);
    cudaGetSymbolAddress((void**)&acth,  g_acth);
    cudaGetSymbolAddress((void**)&wqkvt, g_wqkvt);
    cudaGetSymbolAddress((void**)&bqkv,  g_bqkv);
    cudaGetSymbolAddress((void**)&w1t,   g_w1t);
    cudaGetSymbolAddress((void**)&w2t,   g_w2t);

    cudaFuncSetAttribute(hgemm<0>, cudaFuncAttributeMaxDynamicSharedMemorySize, GEMM_DSMEM);
    cudaFuncSetAttribute(hgemm<1>, cudaFuncAttributeMaxDynamicSharedMemorySize, GEMM_DSMEM);
    cudaFuncSetAttribute(hgemm<2>, cudaFuncAttributeMaxDynamicSharedMemorySize, GEMM_DSMEM);

    // fused preprocessing
    prep_kernel<<<19468, 256>>>(x, Wq, Wk, Wv, W1, W2, bq, bk, bv);

    // fused QKV projection
    hgemm<0><<<dim3(QKVN / 128, ROWS / 256), 256, GEMM_DSMEM>>>(xh, wqkvt, bqkv, nullptr, qkvh, ROWS, QKVN, DD, 0.125f * LOG2E);

    // flash attention (occupancy 2)
    attn_mma<<<dim3(LL / 128, HH, BB), 256>>>(mask);

    // residual + LayerNorm (warp-per-row)
    ln_kernel<<<ROWS / 8, 256>>>(ln_g, ln_b);

    // MLP
    hgemm<1><<<dim3(FF / 128, ROWS / 256), 256, GEMM_DSMEM>>>(hnh, w1t, b1, nullptr, acth, ROWS, FF, DD, 1.0f);
    hgemm<2><<<dim3(DD / 128, ROWS / 256), 256, GEMM_DSMEM>>>(acth, w2t, b2, hnh, out, ROWS, DD, FF, 1.0f);
}